// round 4
// baseline (speedup 1.0000x reference)
#include <cuda_runtime.h>
#include <cuda_fp16.h>
#include <cuda_bf16.h>
#include <string.h>

#define EPS 1e-6f
#define BATCH 64
#define VMAX 100000

typedef unsigned long long ull;

// Scratch: vertices in (V, batch-pair, 8-half record) layout, fp16.
// Vertex v, batch-pair p (batches 2p, 2p+1) occupies halves
// [v*256 + p*8 .. +8): {x0,y0,z0,pad, x1,y1,z1,pad}. 16B-aligned per (v,p).
// Size: 100000 * 256 halves = 51.2 MB.
__device__ __align__(16) __half g_trans_h[VMAX * 256];

// ---------------------------------------------------------------------------
// f32x2 packed-math helpers (FFMA2 path — PTX-only)
// ---------------------------------------------------------------------------
__device__ __forceinline__ ull f2pack(float lo, float hi) {
    ull d;
    asm("mov.b64 %0, {%1, %2};" : "=l"(d)
        : "r"(__float_as_uint(lo)), "r"(__float_as_uint(hi)));
    return d;
}
__device__ __forceinline__ float2 f2unpack(ull v) {
    unsigned lo, hi;
    asm("mov.b64 {%0, %1}, %2;" : "=r"(lo), "=r"(hi) : "l"(v));
    return make_float2(__uint_as_float(lo), __uint_as_float(hi));
}
__device__ __forceinline__ ull f2mul(ull a, ull b) {
    ull d; asm("mul.rn.f32x2 %0, %1, %2;" : "=l"(d) : "l"(a), "l"(b)); return d;
}
__device__ __forceinline__ ull f2add(ull a, ull b) {
    ull d; asm("add.rn.f32x2 %0, %1, %2;" : "=l"(d) : "l"(a), "l"(b)); return d;
}
__device__ __forceinline__ ull f2fma(ull a, ull b, ull c) {
    ull d; asm("fma.rn.f32x2 %0, %1, %2, %3;" : "=l"(d) : "l"(a), "l"(b), "l"(c)); return d;
}
__device__ __forceinline__ ull f2rsqrt(ull v) {
    float2 f = f2unpack(v);
    float lo, hi;
    asm("rsqrt.approx.f32 %0, %1;" : "=f"(lo) : "f"(f.x));
    asm("rsqrt.approx.f32 %0, %1;" : "=f"(hi) : "f"(f.y));
    return f2pack(lo, hi);
}
__device__ __forceinline__ ull f2rcp(ull v) {
    float2 f = f2unpack(v);
    float lo, hi;
    asm("rcp.approx.f32 %0, %1;" : "=f"(lo) : "f"(f.x));
    asm("rcp.approx.f32 %0, %1;" : "=f"(hi) : "f"(f.y));
    return f2pack(lo, hi);
}

__device__ __forceinline__ __half2 u2h2(unsigned u) {
    __half2 h; memcpy(&h, &u, 4); return h;
}

// Parse one 16B vertex record (2 batches) into packed f32x2 coords.
__device__ __forceinline__ void vparse(uint4 r, ull& X, ull& Y, ull& Z) {
    __half2 a = u2h2(r.x);  // (x0, y0)
    __half2 b = u2h2(r.y);  // (z0, pad)
    __half2 c = u2h2(r.z);  // (x1, y1)
    __half2 d = u2h2(r.w);  // (z1, pad)
    X = f2pack(__low2float(a), __low2float(c));
    Y = f2pack(__high2float(a), __high2float(c));
    Z = f2pack(__low2float(b), __low2float(d));
}

// ---------------------------------------------------------------------------
// Transpose (B, V, 3) fp32 -> interleaved fp16 record layout.
// Block = 32 vertices x 64 batches. All index math is compile-time per
// unrolled iteration (no integer div/mod).
// Block 0 additionally zeroes the output (harness poisons with 0xAA).
// ---------------------------------------------------------------------------
__global__ void transpose_kernel(const float* __restrict__ vertices,
                                 float* __restrict__ out, int V, int out_n) {
    __shared__ float tile[BATCH][97];  // [batch][v_local*3+c], pad to 97
    const int v0 = blockIdx.x * 32;
    const int tid = threadIdx.x;

    if (blockIdx.x == 0 && tid < out_n) out[tid] = 0.0f;

    // ---- Load: thread t owns batch b = t>>2, quarter q = t&3 (24 floats) ----
    {
        const int b = tid >> 2;
        const int q = tid & 3;
        const float* src = vertices + (long long)b * (3LL * V)
                         + (long long)v0 * 3 + q * 24;
        const int lim = 3 * (V - v0);  // valid floats in this tile row
        #pragma unroll
        for (int jj = 0; jj < 24; jj++) {
            int j = q * 24 + jj;
            tile[b][j] = (j < lim) ? src[jj] : 0.0f;
        }
    }
    __syncthreads();

    // ---- Store: thread t owns batch-pair b2 = t&31, group g = t>>5 (4 verts) ----
    {
        const int b2 = tid & 31;
        const int g = tid >> 5;
        uint4* dst = (uint4*)(g_trans_h + (long long)v0 * 256);  // 32 uint4 per vertex
        #pragma unroll
        for (int vl = 0; vl < 4; vl++) {
            int v_local = g * 4 + vl;
            if (v0 + v_local < V) {
                int j = v_local * 3;
                float x0 = tile[2 * b2][j], y0 = tile[2 * b2][j + 1], z0 = tile[2 * b2][j + 2];
                float x1 = tile[2 * b2 + 1][j], y1 = tile[2 * b2 + 1][j + 1], z1 = tile[2 * b2 + 1][j + 2];
                __half2 h0 = __floats2half2_rn(x0, y0);
                __half2 h1 = __floats2half2_rn(z0, 0.0f);
                __half2 h2 = __floats2half2_rn(x1, y1);
                __half2 h3 = __floats2half2_rn(z1, 0.0f);
                unsigned u0, u1, u2, u3;
                memcpy(&u0, &h0, 4); memcpy(&u1, &h1, 4);
                memcpy(&u2, &h2, 4); memcpy(&u3, &h3, 4);
                dst[v_local * 32 + b2] = make_uint4(u0, u1, u2, u3);
            }
        }
    }
}

// ---------------------------------------------------------------------------
// Packed loss for 2 batches at once (f32x2 lanes). Matches reference formula;
// EPS folded only where relative perturbation <= ~1e-6 (validated R2/R3).
// ---------------------------------------------------------------------------
__device__ __forceinline__ ull loss2(
    ull p0x, ull p0y, ull p0z, ull p1x, ull p1y, ull p1z,
    ull p2x, ull p2y, ull p2z, ull p3x, ull p3y, ull p3z, ull acc)
{
    const ull M1   = f2pack(-1.0f, -1.0f);
    const ull EPS2 = f2pack(EPS, EPS);
    const ull OPE2 = f2pack(1.0f + EPS, 1.0f + EPS);
    const ull ONE2 = f2pack(1.0f, 1.0f);

    // a = p1 - p0, b1 = p2 - p0, b2 = p3 - p0  (sub via fma with -1)
    ull ax = f2fma(p0x, M1, p1x), ay = f2fma(p0y, M1, p1y), az = f2fma(p0z, M1, p1z);
    ull b1x = f2fma(p0x, M1, p2x), b1y = f2fma(p0y, M1, p2y), b1z = f2fma(p0z, M1, p2z);
    ull b2x = f2fma(p0x, M1, p3x), b2y = f2fma(p0y, M1, p3y), b2z = f2fma(p0z, M1, p3z);

    ull al2 = f2mul(ax, ax); al2 = f2fma(ay, ay, al2); al2 = f2fma(az, az, al2);
    ull al2e = f2add(al2, EPS2);
    ull ral = f2rsqrt(al2e);           // 1/sqrt(al2+EPS)
    ull inv_al2 = f2mul(ral, ral);     // 1/(al2+EPS)

    // wing 1
    ull bl2e1 = f2mul(b1x, b1x); bl2e1 = f2fma(b1y, b1y, bl2e1);
    bl2e1 = f2fma(b1z, b1z, bl2e1); bl2e1 = f2add(bl2e1, EPS2);
    ull rb1 = f2rsqrt(bl2e1);
    ull bl11 = f2mul(bl2e1, rb1);      // sqrt(bl2+EPS)
    ull ab1 = f2mul(ax, b1x); ab1 = f2fma(ay, b1y, ab1); ab1 = f2fma(az, b1z, ab1);
    ull cos1 = f2mul(f2mul(ab1, ral), rb1);
    ull s1 = f2fma(f2mul(cos1, cos1), M1, OPE2);   // 1+EPS - cos^2
    ull t1 = f2mul(ab1, inv_al2);
    ull nt1 = f2mul(t1, M1);
    ull cb1x = f2fma(nt1, ax, b1x);
    ull cb1y = f2fma(nt1, ay, b1y);
    ull cb1z = f2fma(nt1, az, b1z);

    // wing 2
    ull bl2e2 = f2mul(b2x, b2x); bl2e2 = f2fma(b2y, b2y, bl2e2);
    bl2e2 = f2fma(b2z, b2z, bl2e2); bl2e2 = f2add(bl2e2, EPS2);
    ull rb2 = f2rsqrt(bl2e2);
    ull bl12 = f2mul(bl2e2, rb2);
    ull ab2 = f2mul(ax, b2x); ab2 = f2fma(ay, b2y, ab2); ab2 = f2fma(az, b2z, ab2);
    ull cos2 = f2mul(f2mul(ab2, ral), rb2);
    ull s2 = f2fma(f2mul(cos2, cos2), M1, OPE2);
    ull t2 = f2mul(ab2, inv_al2);
    ull nt2 = f2mul(t2, M1);
    ull cb2x = f2fma(nt2, ax, b2x);
    ull cb2y = f2fma(nt2, ay, b2y);
    ull cb2z = f2fma(nt2, az, b2z);

    ull num = f2mul(cb1x, cb2x); num = f2fma(cb1y, cb2y, num); num = f2fma(cb1z, cb2z, num);

    // sin1*sin2 = sqrt(s1*s2): one rsqrt instead of two
    ull s12 = f2mul(s1, s2);
    ull sq12 = f2mul(s12, f2rsqrt(s12));
    ull den = f2fma(f2mul(bl11, bl12), sq12, EPS2);  // cbl1*cbl2 + EPS
    ull c = f2mul(num, f2rcp(den));
    ull u = f2add(c, ONE2);
    return f2fma(u, u, acc);
}

// ---------------------------------------------------------------------------
// Main kernel: one warp per edge (grid-stride); lane l owns batches (2l,2l+1).
// 4 LDG.128 per edge (one 16B record per vertex per lane), fully coalesced.
// ---------------------------------------------------------------------------
__global__ void flatten_loss_kernel(
    const int* __restrict__ v0s, const int* __restrict__ v1s,
    const int* __restrict__ v2s, const int* __restrict__ v3s,
    float* __restrict__ out, int E)
{
    __shared__ float blockAcc[BATCH];
    const int tid = threadIdx.x;
    if (tid < BATCH) blockAcc[tid] = 0.0f;
    __syncthreads();

    const int lane = tid & 31;
    const int warp_global = (blockIdx.x * blockDim.x + tid) >> 5;
    const int nwarps = (gridDim.x * blockDim.x) >> 5;

    const uint4* base = (const uint4*)g_trans_h;  // 32 uint4 per vertex
    ull acc = f2pack(0.0f, 0.0f);

    for (int e = warp_global; e < E; e += nwarps) {
        const int i0 = v0s[e];
        const int i1 = v1s[e];
        const int i2 = v2s[e];
        const int i3 = v3s[e];

        uint4 r0 = base[(long long)i0 * 32 + lane];
        uint4 r1 = base[(long long)i1 * 32 + lane];
        uint4 r2 = base[(long long)i2 * 32 + lane];
        uint4 r3 = base[(long long)i3 * 32 + lane];

        ull p0x, p0y, p0z, p1x, p1y, p1z, p2x, p2y, p2z, p3x, p3y, p3z;
        vparse(r0, p0x, p0y, p0z);
        vparse(r1, p1x, p1y, p1z);
        vparse(r2, p2x, p2y, p2z);
        vparse(r3, p3x, p3y, p3z);

        acc = loss2(p0x, p0y, p0z, p1x, p1y, p1z,
                    p2x, p2y, p2z, p3x, p3y, p3z, acc);
    }

    float2 a = f2unpack(acc);
    atomicAdd(&blockAcc[2 * lane], a.x);
    atomicAdd(&blockAcc[2 * lane + 1], a.y);
    __syncthreads();

    if (tid < BATCH) {
        atomicAdd(&out[tid], blockAcc[tid]);
    }
}

// ---------------------------------------------------------------------------
// Entry point
// ---------------------------------------------------------------------------
extern "C" void kernel_launch(void* const* d_in, const int* in_sizes, int n_in,
                              void* d_out, int out_size)
{
    const float* vertices = (const float*)d_in[0];
    const int* v0s = (const int*)d_in[1];
    const int* v1s = (const int*)d_in[2];
    const int* v2s = (const int*)d_in[3];
    const int* v3s = (const int*)d_in[4];
    float* out = (float*)d_out;

    const int E = in_sizes[1];
    int V = in_sizes[0] / (BATCH * 3);
    if (V > VMAX) V = VMAX;

    transpose_kernel<<<(V + 31) / 32, 256>>>(vertices, out, V, out_size);
    flatten_loss_kernel<<<1184, 256>>>(v0s, v1s, v2s, v3s, out, E);
}

// round 5
// speedup vs baseline: 1.2461x; 1.2461x over previous
#include <cuda_runtime.h>
#include <cuda_fp16.h>
#include <cuda_bf16.h>
#include <string.h>

#define EPS 1e-6f
#define BATCH 64
#define VMAX 100000

typedef unsigned long long ull;

// Scratch: vertices in (V, batch-pair, 8-half record) layout, fp16.
// Vertex v, batch-pair p (batches 2p, 2p+1) occupies halves
// [v*256 + p*8 .. +8): {x0,y0,z0,pad, x1,y1,z1,pad}. 16B-aligned per (v,p).
__device__ __align__(16) __half g_trans_h[VMAX * 256];

// ---------------------------------------------------------------------------
// f32x2 packed-math helpers (FFMA2 path — PTX-only)
// ---------------------------------------------------------------------------
__device__ __forceinline__ ull f2pack(float lo, float hi) {
    ull d;
    asm("mov.b64 %0, {%1, %2};" : "=l"(d)
        : "r"(__float_as_uint(lo)), "r"(__float_as_uint(hi)));
    return d;
}
__device__ __forceinline__ float2 f2unpack(ull v) {
    unsigned lo, hi;
    asm("mov.b64 {%0, %1}, %2;" : "=r"(lo), "=r"(hi) : "l"(v));
    return make_float2(__uint_as_float(lo), __uint_as_float(hi));
}
__device__ __forceinline__ ull f2mul(ull a, ull b) {
    ull d; asm("mul.rn.f32x2 %0, %1, %2;" : "=l"(d) : "l"(a), "l"(b)); return d;
}
__device__ __forceinline__ ull f2add(ull a, ull b) {
    ull d; asm("add.rn.f32x2 %0, %1, %2;" : "=l"(d) : "l"(a), "l"(b)); return d;
}
__device__ __forceinline__ ull f2fma(ull a, ull b, ull c) {
    ull d; asm("fma.rn.f32x2 %0, %1, %2, %3;" : "=l"(d) : "l"(a), "l"(b), "l"(c)); return d;
}
__device__ __forceinline__ ull f2rsqrt(ull v) {
    float2 f = f2unpack(v);
    float lo, hi;
    asm("rsqrt.approx.f32 %0, %1;" : "=f"(lo) : "f"(f.x));
    asm("rsqrt.approx.f32 %0, %1;" : "=f"(hi) : "f"(f.y));
    return f2pack(lo, hi);
}
__device__ __forceinline__ ull f2rcp(ull v) {
    float2 f = f2unpack(v);
    float lo, hi;
    asm("rcp.approx.f32 %0, %1;" : "=f"(lo) : "f"(f.x));
    asm("rcp.approx.f32 %0, %1;" : "=f"(hi) : "f"(f.y));
    return f2pack(lo, hi);
}

__device__ __forceinline__ __half2 u2h2(unsigned u) {
    __half2 h; memcpy(&h, &u, 4); return h;
}

// Parse one 16B vertex record (2 batches) into packed f32x2 coords.
__device__ __forceinline__ void vparse(uint4 r, ull& X, ull& Y, ull& Z) {
    __half2 a = u2h2(r.x);  // (x0, y0)
    __half2 b = u2h2(r.y);  // (z0, pad)
    __half2 c = u2h2(r.z);  // (x1, y1)
    __half2 d = u2h2(r.w);  // (z1, pad)
    X = f2pack(__low2float(a), __low2float(c));
    Y = f2pack(__high2float(a), __high2float(c));
    Z = f2pack(__low2float(b), __low2float(d));
}

// ---------------------------------------------------------------------------
// Transpose (B, V, 3) fp32 -> interleaved fp16 record layout.
// Block = 32 vertices x 64 batches.
// LOAD (R3-proven): linear i -> (b, j): consecutive i = contiguous global
// floats within one batch row -> fully coalesced.
// STORE: linear o -> (v_local, b2): warp writes 32 consecutive uint4 = 512B
// contiguous -> fully coalesced.
// Block 0 additionally zeroes the output (harness poisons with 0xAA).
// ---------------------------------------------------------------------------
__global__ void transpose_kernel(const float* __restrict__ vertices,
                                 float* __restrict__ out, int V, int out_n) {
    __shared__ float tile[BATCH][97];  // [batch][v_local*3+c], pad to 97
    const int v0 = blockIdx.x * 32;
    const int tid = threadIdx.x;

    if (blockIdx.x == 0 && tid < out_n) out[tid] = 0.0f;

    const int lim = 3 * (V - v0);  // valid floats per batch row in this tile

    #pragma unroll
    for (int i = tid; i < BATCH * 96; i += 256) {
        int b = i / 96;
        int j = i - b * 96;
        float val = 0.0f;
        if (j < lim) val = vertices[(long long)b * (3LL * V) + (long long)v0 * 3 + j];
        tile[b][j] = val;
    }
    __syncthreads();

    // 32 vertices * 32 pairs = 1024 uint4 outputs for this block.
    uint4* dst = (uint4*)(g_trans_h + (long long)v0 * 256);  // 32 uint4 per vertex
    #pragma unroll
    for (int o = tid; o < 1024; o += 256) {
        int v_local = o >> 5;
        int b2 = o & 31;
        if (v0 + v_local < V) {
            int j = v_local * 3;
            float x0 = tile[2 * b2][j],     y0 = tile[2 * b2][j + 1],     z0 = tile[2 * b2][j + 2];
            float x1 = tile[2 * b2 + 1][j], y1 = tile[2 * b2 + 1][j + 1], z1 = tile[2 * b2 + 1][j + 2];
            __half2 h0 = __floats2half2_rn(x0, y0);
            __half2 h1 = __floats2half2_rn(z0, 0.0f);
            __half2 h2 = __floats2half2_rn(x1, y1);
            __half2 h3 = __floats2half2_rn(z1, 0.0f);
            unsigned u0, u1, u2, u3;
            memcpy(&u0, &h0, 4); memcpy(&u1, &h1, 4);
            memcpy(&u2, &h2, 4); memcpy(&u3, &h3, 4);
            dst[o] = make_uint4(u0, u1, u2, u3);
        }
    }
}

// ---------------------------------------------------------------------------
// Packed loss for 2 batches at once (f32x2 lanes). Matches reference formula;
// EPS folded only where relative perturbation <= ~1e-6 (validated R2-R4).
// ---------------------------------------------------------------------------
__device__ __forceinline__ ull loss2(
    ull p0x, ull p0y, ull p0z, ull p1x, ull p1y, ull p1z,
    ull p2x, ull p2y, ull p2z, ull p3x, ull p3y, ull p3z, ull acc)
{
    const ull M1   = f2pack(-1.0f, -1.0f);
    const ull EPS2 = f2pack(EPS, EPS);
    const ull OPE2 = f2pack(1.0f + EPS, 1.0f + EPS);
    const ull ONE2 = f2pack(1.0f, 1.0f);

    ull ax = f2fma(p0x, M1, p1x), ay = f2fma(p0y, M1, p1y), az = f2fma(p0z, M1, p1z);
    ull b1x = f2fma(p0x, M1, p2x), b1y = f2fma(p0y, M1, p2y), b1z = f2fma(p0z, M1, p2z);
    ull b2x = f2fma(p0x, M1, p3x), b2y = f2fma(p0y, M1, p3y), b2z = f2fma(p0z, M1, p3z);

    ull al2 = f2mul(ax, ax); al2 = f2fma(ay, ay, al2); al2 = f2fma(az, az, al2);
    ull al2e = f2add(al2, EPS2);
    ull ral = f2rsqrt(al2e);           // 1/sqrt(al2+EPS)
    ull inv_al2 = f2mul(ral, ral);     // 1/(al2+EPS)

    // wing 1
    ull bl2e1 = f2mul(b1x, b1x); bl2e1 = f2fma(b1y, b1y, bl2e1);
    bl2e1 = f2fma(b1z, b1z, bl2e1); bl2e1 = f2add(bl2e1, EPS2);
    ull rb1 = f2rsqrt(bl2e1);
    ull bl11 = f2mul(bl2e1, rb1);      // sqrt(bl2+EPS)
    ull ab1 = f2mul(ax, b1x); ab1 = f2fma(ay, b1y, ab1); ab1 = f2fma(az, b1z, ab1);
    ull cos1 = f2mul(f2mul(ab1, ral), rb1);
    ull s1 = f2fma(f2mul(cos1, cos1), M1, OPE2);   // 1+EPS - cos^2
    ull nt1 = f2mul(f2mul(ab1, inv_al2), M1);
    ull cb1x = f2fma(nt1, ax, b1x);
    ull cb1y = f2fma(nt1, ay, b1y);
    ull cb1z = f2fma(nt1, az, b1z);

    // wing 2
    ull bl2e2 = f2mul(b2x, b2x); bl2e2 = f2fma(b2y, b2y, bl2e2);
    bl2e2 = f2fma(b2z, b2z, bl2e2); bl2e2 = f2add(bl2e2, EPS2);
    ull rb2 = f2rsqrt(bl2e2);
    ull bl12 = f2mul(bl2e2, rb2);
    ull ab2 = f2mul(ax, b2x); ab2 = f2fma(ay, b2y, ab2); ab2 = f2fma(az, b2z, ab2);
    ull cos2 = f2mul(f2mul(ab2, ral), rb2);
    ull s2 = f2fma(f2mul(cos2, cos2), M1, OPE2);
    ull nt2 = f2mul(f2mul(ab2, inv_al2), M1);
    ull cb2x = f2fma(nt2, ax, b2x);
    ull cb2y = f2fma(nt2, ay, b2y);
    ull cb2z = f2fma(nt2, az, b2z);

    ull num = f2mul(cb1x, cb2x); num = f2fma(cb1y, cb2y, num); num = f2fma(cb1z, cb2z, num);

    // sin1*sin2 = sqrt(s1*s2): one rsqrt instead of two
    ull s12 = f2mul(s1, s2);
    ull sq12 = f2mul(s12, f2rsqrt(s12));
    ull den = f2fma(f2mul(bl11, bl12), sq12, EPS2);  // cbl1*cbl2 + EPS
    ull c = f2mul(num, f2rcp(den));
    ull u = f2add(c, ONE2);
    return f2fma(u, u, acc);
}

// ---------------------------------------------------------------------------
// Main kernel: one warp per edge (grid-stride); lane l owns batches (2l,2l+1).
// Software-pipelined: next edge's indices + 4 records are loaded while the
// current edge computes -> 8 LDG.128 in flight per warp.
// ---------------------------------------------------------------------------
__global__ void __launch_bounds__(256)
flatten_loss_kernel(
    const int* __restrict__ v0s, const int* __restrict__ v1s,
    const int* __restrict__ v2s, const int* __restrict__ v3s,
    float* __restrict__ out, int E)
{
    __shared__ float blockAcc[BATCH];
    const int tid = threadIdx.x;
    if (tid < BATCH) blockAcc[tid] = 0.0f;
    __syncthreads();

    const int lane = tid & 31;
    const int warp_global = (blockIdx.x * blockDim.x + tid) >> 5;
    const int nwarps = (gridDim.x * blockDim.x) >> 5;

    const uint4* base = (const uint4*)g_trans_h;  // 32 uint4 per vertex
    ull acc = f2pack(0.0f, 0.0f);

    int e = warp_global;
    uint4 r0, r1, r2, r3;
    if (e < E) {
        int i0 = v0s[e], i1 = v1s[e], i2 = v2s[e], i3 = v3s[e];
        r0 = base[(long long)i0 * 32 + lane];
        r1 = base[(long long)i1 * 32 + lane];
        r2 = base[(long long)i2 * 32 + lane];
        r3 = base[(long long)i3 * 32 + lane];
    }

    while (e < E) {
        const int en = e + nwarps;
        uint4 n0, n1, n2, n3;
        if (en < E) {
            int j0 = v0s[en], j1 = v1s[en], j2 = v2s[en], j3 = v3s[en];
            n0 = base[(long long)j0 * 32 + lane];
            n1 = base[(long long)j1 * 32 + lane];
            n2 = base[(long long)j2 * 32 + lane];
            n3 = base[(long long)j3 * 32 + lane];
        }

        ull p0x, p0y, p0z, p1x, p1y, p1z, p2x, p2y, p2z, p3x, p3y, p3z;
        vparse(r0, p0x, p0y, p0z);
        vparse(r1, p1x, p1y, p1z);
        vparse(r2, p2x, p2y, p2z);
        vparse(r3, p3x, p3y, p3z);
        acc = loss2(p0x, p0y, p0z, p1x, p1y, p1z,
                    p2x, p2y, p2z, p3x, p3y, p3z, acc);

        r0 = n0; r1 = n1; r2 = n2; r3 = n3;
        e = en;
    }

    float2 a = f2unpack(acc);
    atomicAdd(&blockAcc[2 * lane], a.x);
    atomicAdd(&blockAcc[2 * lane + 1], a.y);
    __syncthreads();

    if (tid < BATCH) {
        atomicAdd(&out[tid], blockAcc[tid]);
    }
}

// ---------------------------------------------------------------------------
// Entry point
// ---------------------------------------------------------------------------
extern "C" void kernel_launch(void* const* d_in, const int* in_sizes, int n_in,
                              void* d_out, int out_size)
{
    const float* vertices = (const float*)d_in[0];
    const int* v0s = (const int*)d_in[1];
    const int* v1s = (const int*)d_in[2];
    const int* v2s = (const int*)d_in[3];
    const int* v3s = (const int*)d_in[4];
    float* out = (float*)d_out;

    const int E = in_sizes[1];
    int V = in_sizes[0] / (BATCH * 3);
    if (V > VMAX) V = VMAX;

    transpose_kernel<<<(V + 31) / 32, 256>>>(vertices, out, V, out_size);
    flatten_loss_kernel<<<1184, 256>>>(v0s, v1s, v2s, v3s, out, E);
}

// round 8
// speedup vs baseline: 1.5049x; 1.2077x over previous
#include <cuda_runtime.h>
#include <cuda_fp16.h>
#include <cuda_bf16.h>
#include <string.h>

#define EPS 1e-6f
#define BATCH 64
#define VMAX 100000

typedef unsigned long long ull;

// Scratch: vertices in (V, batch-pair, 8-half record) layout, fp16.
// Vertex v, batch-pair p (batches 2p, 2p+1) occupies halves
// [v*256 + p*8 .. +8): {x0,y0,z0,pad, x1,y1,z1,pad}. 16B-aligned per (v,p).
__device__ __align__(16) __half g_trans_h[VMAX * 256];

// ---------------------------------------------------------------------------
// f32x2 packed-math helpers (FFMA2 path — PTX-only)
// ---------------------------------------------------------------------------
__device__ __forceinline__ ull f2pack(float lo, float hi) {
    ull d;
    asm("mov.b64 %0, {%1, %2};" : "=l"(d)
        : "r"(__float_as_uint(lo)), "r"(__float_as_uint(hi)));
    return d;
}
__device__ __forceinline__ float2 f2unpack(ull v) {
    unsigned lo, hi;
    asm("mov.b64 {%0, %1}, %2;" : "=r"(lo), "=r"(hi) : "l"(v));
    return make_float2(__uint_as_float(lo), __uint_as_float(hi));
}
__device__ __forceinline__ ull f2mul(ull a, ull b) {
    ull d; asm("mul.rn.f32x2 %0, %1, %2;" : "=l"(d) : "l"(a), "l"(b)); return d;
}
__device__ __forceinline__ ull f2add(ull a, ull b) {
    ull d; asm("add.rn.f32x2 %0, %1, %2;" : "=l"(d) : "l"(a), "l"(b)); return d;
}
__device__ __forceinline__ ull f2fma(ull a, ull b, ull c) {
    ull d; asm("fma.rn.f32x2 %0, %1, %2, %3;" : "=l"(d) : "l"(a), "l"(b), "l"(c)); return d;
}
__device__ __forceinline__ ull f2rsqrt(ull v) {
    float2 f = f2unpack(v);
    float lo, hi;
    asm("rsqrt.approx.f32 %0, %1;" : "=f"(lo) : "f"(f.x));
    asm("rsqrt.approx.f32 %0, %1;" : "=f"(hi) : "f"(f.y));
    return f2pack(lo, hi);
}
__device__ __forceinline__ ull f2rcp(ull v) {
    float2 f = f2unpack(v);
    float lo, hi;
    asm("rcp.approx.f32 %0, %1;" : "=f"(lo) : "f"(f.x));
    asm("rcp.approx.f32 %0, %1;" : "=f"(hi) : "f"(f.y));
    return f2pack(lo, hi);
}

__device__ __forceinline__ __half2 u2h2(unsigned u) {
    __half2 h; memcpy(&h, &u, 4); return h;
}

// Difference of two vertex records (fp16 HSUB2), converted to packed f32x2.
// Records: {x0,y0}, {z0,pad}, {x1,y1}, {z1,pad}.
__device__ __forceinline__ void vdiff(uint4 rp, uint4 r0, ull& X, ull& Y, ull& Z) {
    __half2 dxy0 = __hsub2(u2h2(rp.x), u2h2(r0.x));  // (dx0, dy0)
    __half2 dz0  = __hsub2(u2h2(rp.y), u2h2(r0.y));  // (dz0, -)
    __half2 dxy1 = __hsub2(u2h2(rp.z), u2h2(r0.z));  // (dx1, dy1)
    __half2 dz1  = __hsub2(u2h2(rp.w), u2h2(r0.w));  // (dz1, -)
    X = f2pack(__low2float(dxy0),  __low2float(dxy1));
    Y = f2pack(__high2float(dxy0), __high2float(dxy1));
    Z = f2pack(__low2float(dz0),   __low2float(dz1));
}

// ---------------------------------------------------------------------------
// Transpose (B, V, 3) fp32 -> interleaved fp16 record layout (R5-proven).
// Block 0 additionally zeroes the output (harness poisons with 0xAA).
// ---------------------------------------------------------------------------
__global__ void transpose_kernel(const float* __restrict__ vertices,
                                 float* __restrict__ out, int V, int out_n) {
    __shared__ float tile[BATCH][97];  // [batch][v_local*3+c], pad to 97
    const int v0 = blockIdx.x * 32;
    const int tid = threadIdx.x;

    if (blockIdx.x == 0 && tid < out_n) out[tid] = 0.0f;

    const int lim = 3 * (V - v0);

    #pragma unroll
    for (int i = tid; i < BATCH * 96; i += 256) {
        int b = i / 96;
        int j = i - b * 96;
        float val = 0.0f;
        if (j < lim) val = vertices[(long long)b * (3LL * V) + (long long)v0 * 3 + j];
        tile[b][j] = val;
    }
    __syncthreads();

    uint4* dst = (uint4*)(g_trans_h + (long long)v0 * 256);
    #pragma unroll
    for (int o = tid; o < 1024; o += 256) {
        int v_local = o >> 5;
        int b2 = o & 31;
        if (v0 + v_local < V) {
            int j = v_local * 3;
            float x0 = tile[2 * b2][j],     y0 = tile[2 * b2][j + 1],     z0 = tile[2 * b2][j + 2];
            float x1 = tile[2 * b2 + 1][j], y1 = tile[2 * b2 + 1][j + 1], z1 = tile[2 * b2 + 1][j + 2];
            __half2 h0 = __floats2half2_rn(x0, y0);
            __half2 h1 = __floats2half2_rn(z0, 0.0f);
            __half2 h2 = __floats2half2_rn(x1, y1);
            __half2 h3 = __floats2half2_rn(z1, 0.0f);
            unsigned u0, u1, u2, u3;
            memcpy(&u0, &h0, 4); memcpy(&u1, &h1, 4);
            memcpy(&u2, &h2, 4); memcpy(&u3, &h3, 4);
            dst[o] = make_uint4(u0, u1, u2, u3);
        }
    }
}

// ---------------------------------------------------------------------------
// Packed loss, algebraically restructured (exact algebra vs reference):
//   inv = 1/(al2+EPS)
//   cb1.cb2 = b1.b2 - 2*w + w*u,  w = ab1*ab2*inv,  u = al2*inv
//   q_i = bl2e_i*(1+EPS) - ab_i^2*inv   ( = bl2e_i * s_i >= 0 )
//   den = sqrt(q1*q2) + EPS             ( = cbl1*cbl2 + EPS )
// Only 3 MUFU stages (rcp, rsqrt, rcp) per packed pair.
// ---------------------------------------------------------------------------
__device__ __forceinline__ ull loss2(
    ull ax, ull ay, ull az, ull b1x, ull b1y, ull b1z,
    ull b2x, ull b2y, ull b2z, ull acc)
{
    const ull M1   = f2pack(-1.0f, -1.0f);
    const ull M2   = f2pack(-2.0f, -2.0f);
    const ull EPS2 = f2pack(EPS, EPS);
    const ull OPE2 = f2pack(1.0f + EPS, 1.0f + EPS);
    const ull ONE2 = f2pack(1.0f, 1.0f);

    ull al2 = f2mul(ax, ax); al2 = f2fma(ay, ay, al2); al2 = f2fma(az, az, al2);
    ull inv = f2rcp(f2add(al2, EPS2));          // 1/(al2+EPS)

    // wing 1
    ull bl2e1 = f2mul(b1x, b1x); bl2e1 = f2fma(b1y, b1y, bl2e1);
    bl2e1 = f2fma(b1z, b1z, bl2e1); bl2e1 = f2add(bl2e1, EPS2);
    ull ab1 = f2mul(ax, b1x); ab1 = f2fma(ay, b1y, ab1); ab1 = f2fma(az, b1z, ab1);
    ull m1 = f2mul(f2mul(ab1, ab1), inv);       // ab1^2 * inv
    ull q1 = f2fma(m1, M1, f2mul(bl2e1, OPE2)); // bl2e1*(1+EPS) - m1

    // wing 2
    ull bl2e2 = f2mul(b2x, b2x); bl2e2 = f2fma(b2y, b2y, bl2e2);
    bl2e2 = f2fma(b2z, b2z, bl2e2); bl2e2 = f2add(bl2e2, EPS2);
    ull ab2 = f2mul(ax, b2x); ab2 = f2fma(ay, b2y, ab2); ab2 = f2fma(az, b2z, ab2);
    ull m2 = f2mul(f2mul(ab2, ab2), inv);
    ull q2 = f2fma(m2, M1, f2mul(bl2e2, OPE2));

    // numerator: cb1 . cb2
    ull b12 = f2mul(b1x, b2x); b12 = f2fma(b1y, b2y, b12); b12 = f2fma(b1z, b2z, b12);
    ull w = f2mul(f2mul(ab1, ab2), inv);
    ull u = f2mul(al2, inv);
    ull num = f2fma(w, M2, b12);                // b12 - 2w
    num = f2fma(w, u, num);                     // + w*u

    // denominator: sqrt(q1*q2) + EPS
    ull P = f2mul(q1, q2);
    ull sq = f2mul(P, f2rsqrt(P));
    ull den = f2add(sq, EPS2);

    ull c = f2mul(num, f2rcp(den));
    ull t = f2add(c, ONE2);
    return f2fma(t, t, acc);
}

// ---------------------------------------------------------------------------
// Main kernel (R4 simple loop): one warp per edge (grid-stride);
// lane l owns batches (2l, 2l+1). 4 LDG.128 per edge, fully coalesced.
// ---------------------------------------------------------------------------
__global__ void flatten_loss_kernel(
    const int* __restrict__ v0s, const int* __restrict__ v1s,
    const int* __restrict__ v2s, const int* __restrict__ v3s,
    float* __restrict__ out, int E)
{
    __shared__ float blockAcc[BATCH];
    const int tid = threadIdx.x;
    if (tid < BATCH) blockAcc[tid] = 0.0f;
    __syncthreads();

    const int lane = tid & 31;
    const int warp_global = (blockIdx.x * blockDim.x + tid) >> 5;
    const int nwarps = (gridDim.x * blockDim.x) >> 5;

    const uint4* base = (const uint4*)g_trans_h;  // 32 uint4 per vertex
    ull acc = f2pack(0.0f, 0.0f);

    for (int e = warp_global; e < E; e += nwarps) {
        const int i0 = v0s[e];
        const int i1 = v1s[e];
        const int i2 = v2s[e];
        const int i3 = v3s[e];

        uint4 r0 = base[(long long)i0 * 32 + lane];
        uint4 r1 = base[(long long)i1 * 32 + lane];
        uint4 r2 = base[(long long)i2 * 32 + lane];
        uint4 r3 = base[(long long)i3 * 32 + lane];

        ull ax, ay, az, b1x, b1y, b1z, b2x, b2y, b2z;
        vdiff(r1, r0, ax, ay, az);
        vdiff(r2, r0, b1x, b1y, b1z);
        vdiff(r3, r0, b2x, b2y, b2z);

        acc = loss2(ax, ay, az, b1x, b1y, b1z, b2x, b2y, b2z, acc);
    }

    float2 a = f2unpack(acc);
    atomicAdd(&blockAcc[2 * lane], a.x);
    atomicAdd(&blockAcc[2 * lane + 1], a.y);
    __syncthreads();

    if (tid < BATCH) {
        atomicAdd(&out[tid], blockAcc[tid]);
    }
}

// ---------------------------------------------------------------------------
// Entry point
// ---------------------------------------------------------------------------
extern "C" void kernel_launch(void* const* d_in, const int* in_sizes, int n_in,
                              void* d_out, int out_size)
{
    const float* vertices = (const float*)d_in[0];
    const int* v0s = (const int*)d_in[1];
    const int* v1s = (const int*)d_in[2];
    const int* v2s = (const int*)d_in[3];
    const int* v3s = (const int*)d_in[4];
    float* out = (float*)d_out;

    const int E = in_sizes[1];
    int V = in_sizes[0] / (BATCH * 3);
    if (V > VMAX) V = VMAX;

    transpose_kernel<<<(V + 31) / 32, 256>>>(vertices, out, V, out_size);
    flatten_loss_kernel<<<1480, 256>>>(v0s, v1s, v2s, v3s, out, E);
}